// round 15
// baseline (speedup 1.0000x reference)
#include <cuda_runtime.h>
#include <cuda_bf16.h>
#include <cstdint>
#include <cstddef>

// ---------------------------------------------------------------------------
// ContrastiveLoss: loss = mean_i( log(sum_j exp(cos(o_i,t_j))) - cos(o_i,t_i) )
// B = 16384, D = 256, fp32 in, fp32 scalar out.
//
// SINGLE persistent kernel (148 CTAs x 256 threads), three phases with
// in-kernel grid barriers. Phase 2 warp tile is now 64x32 (2x4 grid of 8
// warps): smem LDSM traffic per 128x128 tile drops 512KB -> 384KB, pushing
// the binder from the shared-memory crossbar (ncu: L1 65%, tensor 61%) to
// the tensor pipe. Accumulator ping-pong epilogue (exp under MMA) kept.
// ---------------------------------------------------------------------------

#define NROW   16384
#define DDIM   256
#define NCHUNK 8              // column chunks per row-block
#define TPJ    16             // tiles per job (128 / NCHUNK)
#define NJOBS  1024           // 128 row-blocks * NCHUNK
#define NSM    148
#define NTHR   256

static __device__ __align__(16) __nv_bfloat16 g_obf[NROW * DDIM];
static __device__ __align__(16) __nv_bfloat16 g_tbf[NROW * DDIM];
static __device__ float g_diag[NROW];
static __device__ float g_psum[NJOBS * 128];   // [iblk*8 + cchk][row]
static __device__ unsigned int g_barcnt = 0;   // monotonic grid-barrier ticket

// SMEM layout: A 64KB resident, B0/B1 64KB each, reduction scratch.
#define OFF_A    0
#define OFF_B0   65536
#define OFF_B1   131072
#define OFF_RED  196608   // 512 floats
#define SMEM_DYN 198656

// ---------------------------------------------------------------------------
__device__ __forceinline__ uint32_t smem_u32(const void* p) {
    uint32_t a;
    asm("{ .reg .u64 t; cvta.to.shared.u64 t, %1; cvt.u32.u64 %0, t; }"
        : "=r"(a) : "l"(p));
    return a;
}
__device__ __forceinline__ void cp16(uint32_t dst, const void* src) {
    asm volatile("cp.async.cg.shared.global [%0], [%1], 16;" :: "r"(dst), "l"(src));
}
__device__ __forceinline__ void cp_commit() {
    asm volatile("cp.async.commit_group;" ::: "memory");
}
__device__ __forceinline__ void cp_wait0() {
    asm volatile("cp.async.wait_group 0;" ::: "memory");
}
__device__ __forceinline__ void ldm4(uint32_t* r, uint32_t addr) {
    asm volatile("ldmatrix.sync.aligned.m8n8.x4.shared.b16 {%0,%1,%2,%3}, [%4];"
                 : "=r"(r[0]), "=r"(r[1]), "=r"(r[2]), "=r"(r[3]) : "r"(addr));
}
__device__ __forceinline__ void mma16816(float* d, const uint32_t* a,
                                         uint32_t b0, uint32_t b1) {
    asm volatile(
        "mma.sync.aligned.m16n8k16.row.col.f32.bf16.bf16.f32 "
        "{%0,%1,%2,%3}, {%4,%5,%6,%7}, {%8,%9}, {%0,%1,%2,%3};"
        : "+f"(d[0]), "+f"(d[1]), "+f"(d[2]), "+f"(d[3])
        : "r"(a[0]), "r"(a[1]), "r"(a[2]), "r"(a[3]), "r"(b0), "r"(b1));
}

// Copy one 128x256 bf16 tile (64KB) into swizzled SMEM. 256 threads x 16 chunks.
__device__ __forceinline__ void tile_cp(const uint4* __restrict__ src,
                                        uint32_t dstbase, int tid) {
#pragma unroll
    for (int i = 0; i < 16; i++) {
        int c   = tid + (i << 8);
        int row = c >> 5, k16 = c & 31;
        cp16(dstbase + (row << 9) + ((k16 ^ (row & 7)) << 4), src + c);
    }
}

// Grid-wide barrier. Safe: grid=148 = 1 CTA/SM, all co-resident.
// Monotonic ticket counter -> works across CUDA-graph replays (no reset).
__device__ __forceinline__ void grid_bar(int tid) {
    __syncthreads();
    __threadfence();
    if (tid == 0) {
        unsigned int t = atomicAdd(&g_barcnt, 1u);
        unsigned int target = (t / NSM + 1u) * NSM;
        unsigned int v;
        do {
            asm volatile("ld.acquire.gpu.u32 %0, [%1];"
                         : "=r"(v) : "l"(&g_barcnt));
        } while (v < target);
    }
    __syncthreads();
}

// DC: accumulating set (this tile). DE: set being epilogued (previous tile).
// Warp tile 64x32: 4 A-ldm4 + 2 B-ldm4, 8 HMMA per kstep. 64 accumulator
// elements per set -> 4 exp-elements of DE interleaved per kstep.
#define TILE_BODY(DC, DE, BOFFS, EPI)                                         \
    do {                                                                      \
        const uint32_t bbase_ = sb + (BOFFS);                                 \
        _Pragma("unroll")                                                     \
        for (int ks = 0; ks < 16; ks++) {                                     \
            const uint32_t csel = (uint32_t)((((ks << 1) + lhi) ^ x7) << 4);  \
            uint32_t A4[4][4], Bm[2][4];                                      \
            _Pragma("unroll")                                                 \
            for (int mf = 0; mf < 4; mf++) ldm4(A4[mf], aoff[mf] + csel);     \
            _Pragma("unroll")                                                 \
            for (int p = 0; p < 2; p++)    ldm4(Bm[p], bbase_ + boff[p] + csel); \
            _Pragma("unroll")                                                 \
            for (int mf = 0; mf < 4; mf++)                                    \
                _Pragma("unroll")                                             \
                for (int p = 0; p < 2; p++) {                                 \
                    mma16816(DC[mf][2 * p],     A4[mf], Bm[p][0], Bm[p][2]);  \
                    mma16816(DC[mf][2 * p + 1], A4[mf], Bm[p][1], Bm[p][3]);  \
                }                                                             \
            if (EPI) {                                                        \
                _Pragma("unroll")                                             \
                for (int i = 0; i < 4; i++) {                                 \
                    const int e  = 4 * ks + i;                                \
                    const int mf = e >> 4, nf = (e >> 2) & 3, r = e & 3;      \
                    float v = DE[mf][nf][r];                                  \
                    DE[mf][nf][r] = 0.f;                                      \
                    sums[mf * 2 + (r >> 1)] += __expf(v);                     \
                }                                                             \
            }                                                                 \
        }                                                                     \
    } while (0)

// ---------------------------------------------------------------------------
__global__ void __launch_bounds__(NTHR, 1) ContrastiveAll(
        const float* __restrict__ O, const float* __restrict__ T,
        float* __restrict__ out) {
    extern __shared__ char smem[];
    const uint32_t sb = smem_u32(smem);
    const int tid  = threadIdx.x;
    const int lane = tid & 31, w = tid >> 5;

    // ===================== Phase 1: normalize + diag =====================
    // warp-per-row; 148*8 = 1184 warps cover 16384 rows in ~14 steps.
    for (int r = blockIdx.x * 8 + w; r < NROW; r += NSM * 8) {
        const float4* o4 = (const float4*)(O + (size_t)r * DDIM) + lane * 2;
        const float4* t4 = (const float4*)(T + (size_t)r * DDIM) + lane * 2;
        float4 a0 = o4[0], a1 = o4[1];
        float4 b0 = t4[0], b1 = t4[1];

        float so = a0.x*a0.x + a0.y*a0.y + a0.z*a0.z + a0.w*a0.w
                 + a1.x*a1.x + a1.y*a1.y + a1.z*a1.z + a1.w*a1.w;
        float st = b0.x*b0.x + b0.y*b0.y + b0.z*b0.z + b0.w*b0.w
                 + b1.x*b1.x + b1.y*b1.y + b1.z*b1.z + b1.w*b1.w;
#pragma unroll
        for (int s = 16; s; s >>= 1) {
            so += __shfl_xor_sync(0xffffffffu, so, s);
            st += __shfl_xor_sync(0xffffffffu, st, s);
        }
        const float io = rsqrtf(so), it = rsqrtf(st);

        __nv_bfloat162 oc[4], tc[4];
        oc[0] = __floats2bfloat162_rn(a0.x * io, a0.y * io);
        oc[1] = __floats2bfloat162_rn(a0.z * io, a0.w * io);
        oc[2] = __floats2bfloat162_rn(a1.x * io, a1.y * io);
        oc[3] = __floats2bfloat162_rn(a1.z * io, a1.w * io);
        tc[0] = __floats2bfloat162_rn(b0.x * it, b0.y * it);
        tc[1] = __floats2bfloat162_rn(b0.z * it, b0.w * it);
        tc[2] = __floats2bfloat162_rn(b1.x * it, b1.y * it);
        tc[3] = __floats2bfloat162_rn(b1.z * it, b1.w * it);
        ((uint4*)g_obf)[(size_t)r * 32 + lane] = *(uint4*)oc;
        ((uint4*)g_tbf)[(size_t)r * 32 + lane] = *(uint4*)tc;

        float dp = 0.f;
#pragma unroll
        for (int q = 0; q < 4; q++) {
            dp += __bfloat162float(oc[q].x) * __bfloat162float(tc[q].x)
                + __bfloat162float(oc[q].y) * __bfloat162float(tc[q].y);
        }
#pragma unroll
        for (int s = 16; s; s >>= 1) dp += __shfl_xor_sync(0xffffffffu, dp, s);
        if (lane == 0) g_diag[r] = dp;
    }

    grid_bar(tid);

    // ===================== Phase 2: GEMM + exp partial sums ==============
    const int wm = w >> 2, wn = w & 3;            // 2 x 4 warp grid, 64x32 tiles
    const int g  = lane >> 2;
    const int lrow = ((lane >> 3) & 1) * 8 + (lane & 7);
    const int lhi  = lane >> 4;
    const int x7   = lane & 7;

    uint32_t aoff[4], boff[2];
#pragma unroll
    for (int mf = 0; mf < 4; mf++)
        aoff[mf] = sb + OFF_A + (uint32_t)((wm * 64 + mf * 16 + lrow) << 9);
#pragma unroll
    for (int p = 0; p < 2; p++)
        boff[p] = (uint32_t)((wn * 32 + p * 16 + lrow) << 9);

    const int qbeg = (blockIdx.x * NJOBS) / NSM;
    const int qend = ((blockIdx.x + 1) * NJOBS) / NSM;

    float d0[4][4][4], d1[4][4][4];
#pragma unroll
    for (int mf = 0; mf < 4; mf++)
#pragma unroll
        for (int nf = 0; nf < 4; nf++)
#pragma unroll
            for (int r = 0; r < 4; r++) { d0[mf][nf][r] = 0.f; d1[mf][nf][r] = 0.f; }

    int cur_iblk = -1;

#pragma unroll 1
    for (int q = qbeg; q < qend; q++) {
        const int iblk = q >> 3;
        const int j0   = (q & 7) * TPJ;

        // Prologue: A (only when row-block changes) + B(j0)
        if (iblk != cur_iblk) {
            tile_cp((const uint4*)g_obf + (size_t)iblk * 4096, sb + OFF_A, tid);
            cur_iblk = iblk;
        }
        tile_cp((const uint4*)g_tbf + (size_t)j0 * 4096, sb + OFF_B0, tid);
        cp_commit();
        cp_wait0();
        __syncthreads();

        float sums[8];
#pragma unroll
        for (int s = 0; s < 8; s++) sums[s] = 0.f;

        // Tile j0 (set d0, no epilogue); prefetch B(j0+1)
        tile_cp((const uint4*)g_tbf + (size_t)(j0 + 1) * 4096, sb + OFF_B1, tid);
        cp_commit();
        TILE_BODY(d0, d1, OFF_B0, false);
        cp_wait0();
        __syncthreads();

        // Tiles j0+1 .. j0+14 in 7 pairs
#pragma unroll 1
        for (int jp = 0; jp < 7; jp++) {
            tile_cp((const uint4*)g_tbf + (size_t)(j0 + 2 * jp + 2) * 4096,
                    sb + OFF_B0, tid);
            cp_commit();
            TILE_BODY(d1, d0, OFF_B1, true);
            cp_wait0();
            __syncthreads();
            tile_cp((const uint4*)g_tbf + (size_t)(j0 + 2 * jp + 3) * 4096,
                    sb + OFF_B1, tid);
            cp_commit();
            TILE_BODY(d0, d1, OFF_B0, true);
            cp_wait0();
            __syncthreads();
        }

        // Tile j0+15 (set d1 from B1, epi d0), then tail epilogue of d1
        TILE_BODY(d1, d0, OFF_B1, true);
#pragma unroll
        for (int e = 0; e < 64; e++) {
            const int mf = e >> 4, nf = (e >> 2) & 3, r = e & 3;
            sums[mf * 2 + (r >> 1)] += __expf(d1[mf][nf][r]);
            d1[mf][nf][r] = 0.f;
        }

        // ---- partial-sum reduction (deterministic); NO log here ----
#pragma unroll
        for (int s = 0; s < 8; s++) {
            sums[s] += __shfl_xor_sync(0xffffffffu, sums[s], 1);
            sums[s] += __shfl_xor_sync(0xffffffffu, sums[s], 2);
        }
        float* rp = (float*)(smem + OFF_RED);   // [4][128]
        if ((lane & 3) == 0) {
#pragma unroll
            for (int s = 0; s < 8; s++) {
                int row = wm * 64 + (s >> 1) * 16 + (s & 1) * 8 + g;
                rp[wn * 128 + row] = sums[s];
            }
        }
        __syncthreads();
        if (tid < 128) {
            float srow = rp[tid] + rp[128 + tid] + rp[256 + tid] + rp[384 + tid];
            g_psum[(uint32_t)q * 128u + (uint32_t)tid] = srow;
        }
        __syncthreads();   // rp reused next job
    }

    grid_bar(tid);

    // ===================== Phase 3: combine -> loss (CTA 0) ==============
    if (blockIdx.x == 0) {
        float acc = 0.f;
#pragma unroll
        for (int k = 0; k < 64; k++) {
            const int gr  = tid + (k << 8);        // global row
            const int ib  = gr >> 7, row = gr & 127;
            float s = 0.f;
#pragma unroll
            for (int c = 0; c < NCHUNK; c++)
                s += g_psum[(uint32_t)((ib << 3) + c) * 128u + (uint32_t)row];
            acc += __logf(s) - g_diag[gr];
        }
        float* red = (float*)(smem + OFF_RED);     // 256 floats
        red[tid] = acc;
        __syncthreads();
#pragma unroll
        for (int k = 128; k; k >>= 1) {
            if (tid < k) red[tid] += red[tid + k];
            __syncthreads();
        }
        if (tid == 0) out[0] = red[0] / (float)NROW;
    }
}

// ---------------------------------------------------------------------------
extern "C" void kernel_launch(void* const* d_in, const int* in_sizes, int n_in,
                              void* d_out, int out_size) {
    const float* O = (const float*)d_in[0];
    const float* T = (const float*)d_in[1];
    cudaFuncSetAttribute(ContrastiveAll,
                         cudaFuncAttributeMaxDynamicSharedMemorySize, SMEM_DYN);
    ContrastiveAll<<<NSM, NTHR, SMEM_DYN>>>(O, T, (float*)d_out);
}

// round 16
// speedup vs baseline: 1.1204x; 1.1204x over previous
#include <cuda_runtime.h>
#include <cuda_fp16.h>
#include <cstdint>
#include <cstddef>

// ---------------------------------------------------------------------------
// ContrastiveLoss: loss = mean_i( log(sum_j exp(cos(o_i,t_j))) - cos(o_i,t_i) )
// B = 16384, D = 256, fp32 in, fp32 scalar out.
//
// SINGLE persistent kernel (148 CTAs x 512 threads), three phases with
// in-kernel grid barriers. Phase 2: fp16 mma.sync with f16 ACCUMULATORS
// (rate-neutral on sm_100 legacy path, R7) -> accum regs 64 -> 32, giving
// ptxas headroom under the 128-reg cap to software-pipeline LDSM fragments
// across k-steps (R14 was pinned at exactly 128 regs, stalling on
// LDSM->HMMA dependencies: tensor 61%, L1 65%, 6200 cyc/tile vs 4600 floor).
// Warp tile 32x32 (4x4 grid), accumulator ping-pong epilogue kept.
// ---------------------------------------------------------------------------

#define NROW   16384
#define DDIM   256
#define NCHUNK 8              // column chunks per row-block
#define TPJ    16             // tiles per job (128 / NCHUNK)
#define NJOBS  1024           // 128 row-blocks * NCHUNK
#define NSM    148
#define NTHR   512

static __device__ __align__(16) __half g_obf[NROW * DDIM];
static __device__ __align__(16) __half g_tbf[NROW * DDIM];
static __device__ float g_diag[NROW];
static __device__ float g_psum[NJOBS * 128];   // [iblk*8 + cchk][row]
static __device__ unsigned int g_barcnt = 0;   // monotonic grid-barrier ticket

// SMEM layout: A 64KB resident, B0/B1 64KB each, reduction scratch.
#define OFF_A    0
#define OFF_B0   65536
#define OFF_B1   131072
#define OFF_RED  196608   // 512 floats
#define SMEM_DYN 198656

// ---------------------------------------------------------------------------
__device__ __forceinline__ uint32_t smem_u32(const void* p) {
    uint32_t a;
    asm("{ .reg .u64 t; cvta.to.shared.u64 t, %1; cvt.u32.u64 %0, t; }"
        : "=r"(a) : "l"(p));
    return a;
}
__device__ __forceinline__ void cp16(uint32_t dst, const void* src) {
    asm volatile("cp.async.cg.shared.global [%0], [%1], 16;" :: "r"(dst), "l"(src));
}
__device__ __forceinline__ void cp_commit() {
    asm volatile("cp.async.commit_group;" ::: "memory");
}
__device__ __forceinline__ void cp_wait0() {
    asm volatile("cp.async.wait_group 0;" ::: "memory");
}
__device__ __forceinline__ void ldm4(uint32_t* r, uint32_t addr) {
    asm volatile("ldmatrix.sync.aligned.m8n8.x4.shared.b16 {%0,%1,%2,%3}, [%4];"
                 : "=r"(r[0]), "=r"(r[1]), "=r"(r[2]), "=r"(r[3]) : "r"(addr));
}
// f16-accumulator MMA: D(16x8,f16) += A(16x16,f16) x B(16x8,f16)
__device__ __forceinline__ void mma16816_f16(uint32_t& d0, uint32_t& d1,
                                             const uint32_t* a,
                                             uint32_t b0, uint32_t b1) {
    asm volatile(
        "mma.sync.aligned.m16n8k16.row.col.f16.f16.f16.f16 "
        "{%0,%1}, {%2,%3,%4,%5}, {%6,%7}, {%0,%1};"
        : "+r"(d0), "+r"(d1)
        : "r"(a[0]), "r"(a[1]), "r"(a[2]), "r"(a[3]), "r"(b0), "r"(b1));
}

// Copy one 128x256 fp16 tile (64KB) into swizzled SMEM. 512 threads x 8 chunks.
__device__ __forceinline__ void tile_cp(const uint4* __restrict__ src,
                                        uint32_t dstbase, int tid) {
#pragma unroll
    for (int i = 0; i < 8; i++) {
        int c   = tid + (i << 9);
        int row = c >> 5, k16 = c & 31;
        cp16(dstbase + (row << 9) + ((k16 ^ (row & 7)) << 4), src + c);
    }
}

// Grid-wide barrier. Safe: grid=148 = 1 CTA/SM, all co-resident.
// Monotonic ticket counter -> works across CUDA-graph replays (no reset).
__device__ __forceinline__ void grid_bar(int tid) {
    __syncthreads();
    __threadfence();
    if (tid == 0) {
        unsigned int t = atomicAdd(&g_barcnt, 1u);
        unsigned int target = (t / NSM + 1u) * NSM;
        unsigned int v;
        do {
            asm volatile("ld.acquire.gpu.u32 %0, [%1];"
                         : "=r"(v) : "l"(&g_barcnt));
        } while (v < target);
    }
    __syncthreads();
}

// DC: accumulating set (this tile), uint32 [2][4][2] (f16x2; [.][.][h] = row
// group h). DE: set being epilogued. One DE uint32 (2 elems) per k-step.
#define TILE_BODY(DC, DE, BOFFS, EPI)                                         \
    do {                                                                      \
        const uint32_t bbase_ = sb + (BOFFS);                                 \
        _Pragma("unroll")                                                     \
        for (int ks = 0; ks < 16; ks++) {                                     \
            const uint32_t csel = (uint32_t)((((ks << 1) + lhi) ^ x7) << 4);  \
            uint32_t A2[2][4], Bm[2][4];                                      \
            _Pragma("unroll")                                                 \
            for (int mf = 0; mf < 2; mf++) ldm4(A2[mf], aoff[mf] + csel);     \
            _Pragma("unroll")                                                 \
            for (int p = 0; p < 2; p++)    ldm4(Bm[p], bbase_ + boff[p] + csel); \
            _Pragma("unroll")                                                 \
            for (int mf = 0; mf < 2; mf++)                                    \
                _Pragma("unroll")                                             \
                for (int p = 0; p < 2; p++) {                                 \
                    mma16816_f16(DC[mf][2*p][0],   DC[mf][2*p][1],            \
                                 A2[mf], Bm[p][0], Bm[p][2]);                 \
                    mma16816_f16(DC[mf][2*p+1][0], DC[mf][2*p+1][1],          \
                                 A2[mf], Bm[p][1], Bm[p][3]);                 \
                }                                                             \
            if (EPI) {                                                        \
                const int emf = ks >> 3, enf = (ks >> 1) & 3, eh = ks & 1;    \
                float2 f = __half22float2(                                    \
                    *reinterpret_cast<__half2*>(&DE[emf][enf][eh]));          \
                DE[emf][enf][eh] = 0u;                                        \
                sums[emf * 2 + eh] += __expf(f.x) + __expf(f.y);              \
            }                                                                 \
        }                                                                     \
    } while (0)

// ---------------------------------------------------------------------------
__global__ void __launch_bounds__(NTHR, 1) ContrastiveAll(
        const float* __restrict__ O, const float* __restrict__ T,
        float* __restrict__ out) {
    extern __shared__ char smem[];
    const uint32_t sb = smem_u32(smem);
    const int tid  = threadIdx.x;
    const int lane = tid & 31, w = tid >> 5;

    // ===================== Phase 1: normalize + diag =====================
    // warp-per-row; 148*16 = 2368 warps cover 16384 rows in ~7 steps.
    for (int r = blockIdx.x * 16 + w; r < NROW; r += NSM * 16) {
        const float4* o4 = (const float4*)(O + (size_t)r * DDIM) + lane * 2;
        const float4* t4 = (const float4*)(T + (size_t)r * DDIM) + lane * 2;
        float4 a0 = o4[0], a1 = o4[1];
        float4 b0 = t4[0], b1 = t4[1];

        float so = a0.x*a0.x + a0.y*a0.y + a0.z*a0.z + a0.w*a0.w
                 + a1.x*a1.x + a1.y*a1.y + a1.z*a1.z + a1.w*a1.w;
        float st = b0.x*b0.x + b0.y*b0.y + b0.z*b0.z + b0.w*b0.w
                 + b1.x*b1.x + b1.y*b1.y + b1.z*b1.z + b1.w*b1.w;
#pragma unroll
        for (int s = 16; s; s >>= 1) {
            so += __shfl_xor_sync(0xffffffffu, so, s);
            st += __shfl_xor_sync(0xffffffffu, st, s);
        }
        const float io = rsqrtf(so), it = rsqrtf(st);

        __half2 oc[4], tc[4];
        oc[0] = __floats2half2_rn(a0.x * io, a0.y * io);
        oc[1] = __floats2half2_rn(a0.z * io, a0.w * io);
        oc[2] = __floats2half2_rn(a1.x * io, a1.y * io);
        oc[3] = __floats2half2_rn(a1.z * io, a1.w * io);
        tc[0] = __floats2half2_rn(b0.x * it, b0.y * it);
        tc[1] = __floats2half2_rn(b0.z * it, b0.w * it);
        tc[2] = __floats2half2_rn(b1.x * it, b1.y * it);
        tc[3] = __floats2half2_rn(b1.z * it, b1.w * it);
        ((uint4*)g_obf)[(size_t)r * 32 + lane] = *(uint4*)oc;
        ((uint4*)g_tbf)[(size_t)r * 32 + lane] = *(uint4*)tc;

        float dp = 0.f;
#pragma unroll
        for (int q = 0; q < 4; q++) {
            dp += __half2float(oc[q].x) * __half2float(tc[q].x)
                + __half2float(oc[q].y) * __half2float(tc[q].y);
        }
#pragma unroll
        for (int s = 16; s; s >>= 1) dp += __shfl_xor_sync(0xffffffffu, dp, s);
        if (lane == 0) g_diag[r] = dp;
    }

    grid_bar(tid);

    // ===================== Phase 2: GEMM + exp partial sums ==============
    const int wm = w >> 2, wn = w & 3;            // 4 x 4 warp grid
    const int g  = lane >> 2;
    const int lrow = ((lane >> 3) & 1) * 8 + (lane & 7);
    const int lhi  = lane >> 4;
    const int x7   = lane & 7;

    uint32_t aoff[2], boff[2];
#pragma unroll
    for (int mf = 0; mf < 2; mf++)
        aoff[mf] = sb + OFF_A + (uint32_t)((wm * 32 + mf * 16 + lrow) << 9);
#pragma unroll
    for (int p = 0; p < 2; p++)
        boff[p] = (uint32_t)((wn * 32 + p * 16 + lrow) << 9);

    const int qbeg = (blockIdx.x * NJOBS) / NSM;
    const int qend = ((blockIdx.x + 1) * NJOBS) / NSM;

    // f16x2 accumulators: [mf][nf][h], h = row group (g / g+8)
    uint32_t d0[2][4][2], d1[2][4][2];
#pragma unroll
    for (int mf = 0; mf < 2; mf++)
#pragma unroll
        for (int nf = 0; nf < 4; nf++)
#pragma unroll
            for (int h = 0; h < 2; h++) { d0[mf][nf][h] = 0u; d1[mf][nf][h] = 0u; }

    int cur_iblk = -1;

#pragma unroll 1
    for (int q = qbeg; q < qend; q++) {
        const int iblk = q >> 3;
        const int j0   = (q & 7) * TPJ;

        // Prologue: A (only when row-block changes) + B(j0)
        if (iblk != cur_iblk) {
            tile_cp((const uint4*)g_obf + (size_t)iblk * 4096, sb + OFF_A, tid);
            cur_iblk = iblk;
        }
        tile_cp((const uint4*)g_tbf + (size_t)j0 * 4096, sb + OFF_B0, tid);
        cp_commit();
        cp_wait0();
        __syncthreads();

        float sums[4];
#pragma unroll
        for (int s = 0; s < 4; s++) sums[s] = 0.f;

        // Tile j0 (set d0, no epilogue); prefetch B(j0+1)
        tile_cp((const uint4*)g_tbf + (size_t)(j0 + 1) * 4096, sb + OFF_B1, tid);
        cp_commit();
        TILE_BODY(d0, d1, OFF_B0, false);
        cp_wait0();
        __syncthreads();

        // Tiles j0+1 .. j0+14 in 7 pairs
#pragma unroll 1
        for (int jp = 0; jp < 7; jp++) {
            tile_cp((const uint4*)g_tbf + (size_t)(j0 + 2 * jp + 2) * 4096,
                    sb + OFF_B0, tid);
            cp_commit();
            TILE_BODY(d1, d0, OFF_B1, true);
            cp_wait0();
            __syncthreads();
            tile_cp((const uint4*)g_tbf + (size_t)(j0 + 2 * jp + 3) * 4096,
                    sb + OFF_B1, tid);
            cp_commit();
            TILE_BODY(d0, d1, OFF_B0, true);
            cp_wait0();
            __syncthreads();
        }

        // Tile j0+15 (set d1 from B1, epi d0), then tail epilogue of d1
        TILE_BODY(d1, d0, OFF_B1, true);
#pragma unroll
        for (int e = 0; e < 16; e++) {
            const int emf = e >> 3, enf = (e >> 1) & 3, eh = e & 1;
            float2 f = __half22float2(
                *reinterpret_cast<__half2*>(&d1[emf][enf][eh]));
            d1[emf][enf][eh] = 0u;
            sums[emf * 2 + eh] += __expf(f.x) + __expf(f.y);
        }

        // ---- partial-sum reduction (deterministic); NO log here ----
#pragma unroll
        for (int s = 0; s < 4; s++) {
            sums[s] += __shfl_xor_sync(0xffffffffu, sums[s], 1);
            sums[s] += __shfl_xor_sync(0xffffffffu, sums[s], 2);
        }
        float* rp = (float*)(smem + OFF_RED);   // [4][128]
        if ((lane & 3) == 0) {
#pragma unroll
            for (int s = 0; s < 4; s++) {
                int row = wm * 32 + (s >> 1) * 16 + (s & 1) * 8 + g;
                rp[wn * 128 + row] = sums[s];
            }
        }
        __syncthreads();
        if (tid < 128) {
            float srow = rp[tid] + rp[128 + tid] + rp[256 + tid] + rp[384 + tid];
            g_psum[(uint32_t)q * 128u + (uint32_t)tid] = srow;
        }
        __syncthreads();   // rp reused next job
    }

    grid_bar(tid);

    // ===================== Phase 3: combine -> loss (CTA 0) ==============
    if (blockIdx.x == 0) {
        float acc = 0.f;
#pragma unroll
        for (int k = 0; k < 32; k++) {
            const int gr  = tid + (k << 9);        // global row
            const int ib  = gr >> 7, row = gr & 127;
            float s = 0.f;
#pragma unroll
            for (int c = 0; c < NCHUNK; c++)
                s += g_psum[(uint32_t)((ib << 3) + c) * 128u + (uint32_t)row];
            acc += __logf(s) - g_diag[gr];
        }
        float* red = (float*)(smem + OFF_RED);     // 512 floats
        red[tid] = acc;
        __syncthreads();
#pragma unroll
        for (int k = 256; k; k >>= 1) {
            if (tid < k) red[tid] += red[tid + k];
            __syncthreads();
        }
        if (tid == 0) out[0] = red[0] / (float)NROW;
    }
}

// ---------------------------------------------------------------------------
extern "C" void kernel_launch(void* const* d_in, const int* in_sizes, int n_in,
                              void* d_out, int out_size) {
    const float* O = (const float*)d_in[0];
    const float* T = (const float*)d_in[1];
    cudaFuncSetAttribute(ContrastiveAll,
                         cudaFuncAttributeMaxDynamicSharedMemorySize, SMEM_DYN);
    ContrastiveAll<<<NSM, NTHR, SMEM_DYN>>>(O, T, (float*)d_out);
}